// round 4
// baseline (speedup 1.0000x reference)
#include <cuda_runtime.h>
#include <math.h>

// ---------------------------------------------------------------------------
// Attention_51977694216863: single-head causal attention
//   B=4, S=2048, D=2048, fp32
//   q = x@Wq^T + bq ; k = x@Wk^T + bk ; v = x@Wv^T + bv
//   scores = (q@k^T)/sqrt(D), causal mask, softmax
//   ctx = attn@v ; out = ctx@Wp^T + bp
// fp32 register-tiled SGEMM pipeline with causal block skipping.
// Scratch reduced to 4 x 64MB via liveness reuse (q buffer reused for ctx).
// ---------------------------------------------------------------------------

#define BM 128
#define BN 128
#define BK 16
#define TM 8
#define TN 8
#define NT 256

// Scratch (allocation-free rule: __device__ globals).
// g_qc: holds q for the scores GEMM, then is reused for ctx (q dead by then).
__device__ float g_qc[8192L * 2048];
__device__ float g_k [8192L * 2048];
__device__ float g_v [8192L * 2048];
__device__ float g_s [4L * 2048 * 2048];

// ---------------------------------------------------------------------------
// TN GEMM: C[b] = scale * (A[b] @ B[b]^T) (+ bias)  [+ causal mask to -inf]
// A: [M,K] row-major, B: [N,K] row-major, C: [M,N] row-major.
// All dims are multiples of 128/16 for this problem (no bounds checks).
// ---------------------------------------------------------------------------
template <bool CAUSAL, bool HAS_BIAS>
__global__ void __launch_bounds__(NT)
gemm_tn_kernel(const float* __restrict__ A, const float* __restrict__ B,
               const float* __restrict__ bias, float* __restrict__ C,
               int M, int N, int K, float scale,
               long sA, long sB, long sC)
{
    const int bm0 = blockIdx.y * BM;
    const int bn0 = blockIdx.x * BN;
    const int tid = threadIdx.x;
    const int tx = tid & 15, ty = tid >> 4;
    const int row0 = ty * TM, col0 = tx * TN;

    A += (long)blockIdx.z * sA;
    B += (long)blockIdx.z * sB;
    C += (long)blockIdx.z * sC;

    if (CAUSAL && bn0 >= bm0 + BM) {
        // Entire tile strictly above the diagonal: write -inf, skip compute.
        const float NEG = -INFINITY;
        const float4 m4 = make_float4(NEG, NEG, NEG, NEG);
        #pragma unroll
        for (int i = 0; i < TM; ++i) {
            float4* crow = (float4*)(C + (long)(bm0 + row0 + i) * N + bn0 + col0);
            crow[0] = m4;
            crow[1] = m4;
        }
        return;
    }

    __shared__ float As[BK][BM];
    __shared__ float Bs[BK][BN];

    float acc[TM][TN] = {};

    // Tile-load mapping: 128x16 tile = 512 float4 along K; 2 per thread.
    const int lr0 = tid >> 2;        // rows 0..63
    const int lr1 = lr0 + 64;        // rows 64..127
    const int lkq = (tid & 3) * 4;   // k offset within tile: 0,4,8,12

    for (int k0 = 0; k0 < K; k0 += BK) {
        float4 a0 = *(const float4*)(A + (long)(bm0 + lr0) * K + k0 + lkq);
        float4 a1 = *(const float4*)(A + (long)(bm0 + lr1) * K + k0 + lkq);
        float4 b0 = *(const float4*)(B + (long)(bn0 + lr0) * K + k0 + lkq);
        float4 b1 = *(const float4*)(B + (long)(bn0 + lr1) * K + k0 + lkq);

        As[lkq + 0][lr0] = a0.x; As[lkq + 1][lr0] = a0.y;
        As[lkq + 2][lr0] = a0.z; As[lkq + 3][lr0] = a0.w;
        As[lkq + 0][lr1] = a1.x; As[lkq + 1][lr1] = a1.y;
        As[lkq + 2][lr1] = a1.z; As[lkq + 3][lr1] = a1.w;
        Bs[lkq + 0][lr0] = b0.x; Bs[lkq + 1][lr0] = b0.y;
        Bs[lkq + 2][lr0] = b0.z; Bs[lkq + 3][lr0] = b0.w;
        Bs[lkq + 0][lr1] = b1.x; Bs[lkq + 1][lr1] = b1.y;
        Bs[lkq + 2][lr1] = b1.z; Bs[lkq + 3][lr1] = b1.w;
        __syncthreads();

        #pragma unroll
        for (int kk = 0; kk < BK; ++kk) {
            float ar[TM], br[TN];
            *(float4*)&ar[0] = *(const float4*)&As[kk][row0];
            *(float4*)&ar[4] = *(const float4*)&As[kk][row0 + 4];
            *(float4*)&br[0] = *(const float4*)&Bs[kk][col0];
            *(float4*)&br[4] = *(const float4*)&Bs[kk][col0 + 4];
            #pragma unroll
            for (int i = 0; i < TM; ++i)
                #pragma unroll
                for (int j = 0; j < TN; ++j)
                    acc[i][j] += ar[i] * br[j];
        }
        __syncthreads();
    }

    float bvv[TN];
    #pragma unroll
    for (int j = 0; j < TN; ++j)
        bvv[j] = HAS_BIAS ? bias[bn0 + col0 + j] : 0.0f;

    #pragma unroll
    for (int i = 0; i < TM; ++i) {
        const int r = bm0 + row0 + i;
        float outv[TN];
        #pragma unroll
        for (int j = 0; j < TN; ++j) {
            float vv = acc[i][j] * scale + bvv[j];
            if (CAUSAL && (bn0 + col0 + j) > r) vv = -INFINITY;
            outv[j] = vv;
        }
        float4* crow = (float4*)(C + (long)r * N + bn0 + col0);
        crow[0] = *(float4*)&outv[0];
        crow[1] = *(float4*)&outv[4];
    }
}

// ---------------------------------------------------------------------------
// NN GEMM: C[b] = A[b] @ B[b]
// A: [M,K] row-major, B: [K,N] row-major, C: [M,N] row-major.
// KLIMIT: causal attn rows q in [bm0,bm0+127] have attn[q,k]=0 for k>q,
// so the K loop only needs to run to bm0+BM.
// ---------------------------------------------------------------------------
template <bool KLIMIT>
__global__ void __launch_bounds__(NT)
gemm_nn_kernel(const float* __restrict__ A, const float* __restrict__ B,
               float* __restrict__ C, int M, int N, int K,
               long sA, long sB, long sC)
{
    const int bm0 = blockIdx.y * BM;
    const int bn0 = blockIdx.x * BN;
    const int tid = threadIdx.x;
    const int tx = tid & 15, ty = tid >> 4;
    const int row0 = ty * TM, col0 = tx * TN;

    A += (long)blockIdx.z * sA;
    B += (long)blockIdx.z * sB;
    C += (long)blockIdx.z * sC;

    __shared__ float As[BK][BM];
    __shared__ float Bs[BK][BN];

    float acc[TM][TN] = {};

    const int lr0 = tid >> 2;
    const int lr1 = lr0 + 64;
    const int lkq = (tid & 3) * 4;
    const int bk0 = tid >> 5;          // B tile rows 0..7
    const int bk1 = bk0 + 8;           // 8..15
    const int bn4 = (tid & 31) * 4;    // cols 0..124

    const int kend = KLIMIT ? min(K, bm0 + BM) : K;

    for (int k0 = 0; k0 < kend; k0 += BK) {
        float4 a0 = *(const float4*)(A + (long)(bm0 + lr0) * K + k0 + lkq);
        float4 a1 = *(const float4*)(A + (long)(bm0 + lr1) * K + k0 + lkq);
        float4 bb0 = *(const float4*)(B + (long)(k0 + bk0) * N + bn0 + bn4);
        float4 bb1 = *(const float4*)(B + (long)(k0 + bk1) * N + bn0 + bn4);

        As[lkq + 0][lr0] = a0.x; As[lkq + 1][lr0] = a0.y;
        As[lkq + 2][lr0] = a0.z; As[lkq + 3][lr0] = a0.w;
        As[lkq + 0][lr1] = a1.x; As[lkq + 1][lr1] = a1.y;
        As[lkq + 2][lr1] = a1.z; As[lkq + 3][lr1] = a1.w;
        *(float4*)&Bs[bk0][bn4] = bb0;
        *(float4*)&Bs[bk1][bn4] = bb1;
        __syncthreads();

        #pragma unroll
        for (int kk = 0; kk < BK; ++kk) {
            float ar[TM], br[TN];
            *(float4*)&ar[0] = *(const float4*)&As[kk][row0];
            *(float4*)&ar[4] = *(const float4*)&As[kk][row0 + 4];
            *(float4*)&br[0] = *(const float4*)&Bs[kk][col0];
            *(float4*)&br[4] = *(const float4*)&Bs[kk][col0 + 4];
            #pragma unroll
            for (int i = 0; i < TM; ++i)
                #pragma unroll
                for (int j = 0; j < TN; ++j)
                    acc[i][j] += ar[i] * br[j];
        }
        __syncthreads();
    }

    #pragma unroll
    for (int i = 0; i < TM; ++i) {
        const int r = bm0 + row0 + i;
        float4* crow = (float4*)(C + (long)r * N + bn0 + col0);
        crow[0] = *(float4*)&acc[i][0];
        crow[1] = *(float4*)&acc[i][4];
    }
}

// ---------------------------------------------------------------------------
// Row softmax over 2048 columns; one block (256 threads) per row.
// Masked entries are -inf (exp -> 0). Every row has >=1 finite entry.
// ---------------------------------------------------------------------------
__global__ void __launch_bounds__(256)
softmax_kernel(float* __restrict__ S)
{
    const long row = blockIdx.x;
    float* p = S + row * 2048L;
    const int tid = threadIdx.x;

    float v[8];
    float m = -INFINITY;
    #pragma unroll
    for (int i = 0; i < 8; ++i) {
        v[i] = p[tid + i * 256];
        m = fmaxf(m, v[i]);
    }
    #pragma unroll
    for (int o = 16; o > 0; o >>= 1)
        m = fmaxf(m, __shfl_xor_sync(0xffffffffu, m, o));

    __shared__ float red[8];
    if ((tid & 31) == 0) red[tid >> 5] = m;
    __syncthreads();
    float mg = red[0];
    #pragma unroll
    for (int w = 1; w < 8; ++w) mg = fmaxf(mg, red[w]);

    float sum = 0.0f;
    #pragma unroll
    for (int i = 0; i < 8; ++i) {
        v[i] = __expf(v[i] - mg);
        sum += v[i];
    }
    #pragma unroll
    for (int o = 16; o > 0; o >>= 1)
        sum += __shfl_xor_sync(0xffffffffu, sum, o);
    __syncthreads();
    if ((tid & 31) == 0) red[tid >> 5] = sum;
    __syncthreads();
    float tot = 0.0f;
    #pragma unroll
    for (int w = 0; w < 8; ++w) tot += red[w];
    const float inv = 1.0f / tot;

    #pragma unroll
    for (int i = 0; i < 8; ++i)
        p[tid + i * 256] = v[i] * inv;
}

// ---------------------------------------------------------------------------
// Launch
// ---------------------------------------------------------------------------
extern "C" void kernel_launch(void* const* d_in, const int* in_sizes, int n_in,
                              void* d_out, int out_size)
{
    const float* x  = (const float*)d_in[0];
    // d_in[1] is the mask; it is exactly causal tril -> applied analytically.
    const float* Wq = (const float*)d_in[2];
    const float* bq = (const float*)d_in[3];
    const float* Wk = (const float*)d_in[4];
    const float* bk = (const float*)d_in[5];
    const float* Wv = (const float*)d_in[6];
    const float* bv = (const float*)d_in[7];
    const float* Wp = (const float*)d_in[8];
    const float* bp = (const float*)d_in[9];
    float* out = (float*)d_out;

    float *qc, *k, *v, *s;
    cudaGetSymbolAddress((void**)&qc, g_qc);
    cudaGetSymbolAddress((void**)&k,  g_k);
    cudaGetSymbolAddress((void**)&v,  g_v);
    cudaGetSymbolAddress((void**)&s,  g_s);

    const int Bt = 4, S2 = 2048, D = 2048;
    const int Mtot = Bt * S2;                  // 8192
    const long ts = (long)S2 * D;              // token-batch stride
    const long bs = (long)S2 * S2;             // scores batch stride
    const float inv_std = 1.0f / sqrtf((float)D);

    dim3 blk(NT);
    dim3 gproj(D / BN, Mtot / BM, 1);          // (16, 64)
    dim3 gattn(S2 / BN, S2 / BM, Bt);          // (16, 16, 4)

    // Projections (q lives in the shared qc buffer).
    gemm_tn_kernel<false, true><<<gproj, blk>>>(x, Wq, bq, qc, Mtot, D, D, 1.0f, 0, 0, 0);
    gemm_tn_kernel<false, true><<<gproj, blk>>>(x, Wk, bk, k,  Mtot, D, D, 1.0f, 0, 0, 0);
    gemm_tn_kernel<false, true><<<gproj, blk>>>(x, Wv, bv, v,  Mtot, D, D, 1.0f, 0, 0, 0);

    // scores = (q @ k^T) * inv_std with causal mask (upper tiles skipped).
    // After this, q (and k) are dead.
    gemm_tn_kernel<true, false><<<gattn, blk>>>(qc, k, nullptr, s, S2, S2, D, inv_std, ts, ts, bs);

    // softmax over rows
    softmax_kernel<<<Bt * S2, 256>>>(s);

    // ctx = attn @ v (K loop limited to causal extent); ctx reuses k's buffer
    // (q's buffer is the A operand of the scores GEMM already consumed; use k's
    //  buffer which is fully dead, to avoid any same-buffer read/write overlap).
    gemm_nn_kernel<true><<<gattn, blk>>>(s, v, k, S2, D, S2, bs, ts, ts);

    // out = ctx @ Wp^T + bp
    gemm_tn_kernel<false, true><<<gproj, blk>>>(k, Wp, bp, out, Mtot, D, D, 1.0f, 0, 0, 0);
}

// round 5
// speedup vs baseline: 2.4534x; 2.4534x over previous
#include <cuda_runtime.h>
#include <cuda_bf16.h>
#include <math.h>
#include <stdint.h>

// ---------------------------------------------------------------------------
// Attention_51977694216863: single-head causal attention (B=4, S=2048, D=2048)
// All GEMMs as ONE bf16x3 split-precision mma.sync TN kernel:
//   C = scale * (A @ B^T) [+ bias(col|row)] [causal mask / causal K-limit]
// bf16x3: a = ahi + alo (bf16 each); D += ahi*bhi + alo*bhi + ahi*blo
// -> rel err ~1e-5, ~4x FFMA throughput per mma-FLOP even at 3x FLOP count.
// V is materialized transposed (vt = Wv @ x^T) so ctx = TN(attn, vt).
// ---------------------------------------------------------------------------

#define BM 128
#define BN 128
#define BK 32
#define NT 256
#define QS 20                    // u32 words per packed smem row (16 used + 4 pad)
#define TILE_W (128 * QS)        // 2560 words = 10240 B per tile
#define SMEM_BYTES (2 * 4 * TILE_W * 4)   // 2 buffers x {Ahi,Alo,Bhi,Blo} = 81920 B

// Scratch (allocation-free rule: __device__ globals)
__device__ float g_qc[8192L * 2048];   // q, later reused for ctx
__device__ float g_k [8192L * 2048];
__device__ float g_vt[2048L * 8192];   // V transposed: [D, B*S]
__device__ float g_s [4L * 2048 * 2048];

// ---------------------------------------------------------------------------
// helpers
// ---------------------------------------------------------------------------
__device__ __forceinline__ uint32_t cvt_bf16x2(float lo_e, float hi_e) {
    uint32_t r;
    asm("cvt.rn.bf16x2.f32 %0, %1, %2;" : "=r"(r) : "f"(hi_e), "f"(lo_e));
    return r;  // low half = lo_e, high half = hi_e
}

// split a float pair (e0,e1) into packed bf16x2 (hi, lo) parts
__device__ __forceinline__ void split2(float e0, float e1, uint32_t& hi, uint32_t& lo) {
    uint32_t h = cvt_bf16x2(e0, e1);
    float f0 = __uint_as_float(h << 16);
    float f1 = __uint_as_float(h & 0xffff0000u);
    lo = cvt_bf16x2(e0 - f0, e1 - f1);
    hi = h;
}

__device__ __forceinline__ void mma_bf16(float* c, uint32_t a0, uint32_t a1,
                                         uint32_t a2, uint32_t a3,
                                         uint32_t b0, uint32_t b1) {
    asm volatile(
        "mma.sync.aligned.m16n8k16.row.col.f32.bf16.bf16.f32 "
        "{%0,%1,%2,%3}, {%4,%5,%6,%7}, {%8,%9}, {%0,%1,%2,%3};"
        : "+f"(c[0]), "+f"(c[1]), "+f"(c[2]), "+f"(c[3])
        : "r"(a0), "r"(a1), "r"(a2), "r"(a3), "r"(b0), "r"(b1));
}

// convert + store one thread's staged tile data (A and B) into a packed buffer
__device__ __forceinline__ void store_tile(uint32_t* buf, const float4* ra,
                                           const float4* rb, int base) {
    uint32_t* Ah = buf;
    uint32_t* Al = buf + TILE_W;
    uint32_t* Bh = buf + 2 * TILE_W;
    uint32_t* Bl = buf + 3 * TILE_W;
    #pragma unroll
    for (int j = 0; j < 4; ++j) {
        uint32_t h0, l0, h1, l1;
        split2(ra[j].x, ra[j].y, h0, l0);
        split2(ra[j].z, ra[j].w, h1, l1);
        *(uint2*)(Ah + base + 2 * j) = make_uint2(h0, h1);
        *(uint2*)(Al + base + 2 * j) = make_uint2(l0, l1);
        split2(rb[j].x, rb[j].y, h0, l0);
        split2(rb[j].z, rb[j].w, h1, l1);
        *(uint2*)(Bh + base + 2 * j) = make_uint2(h0, h1);
        *(uint2*)(Bl + base + 2 * j) = make_uint2(l0, l1);
    }
}

// ---------------------------------------------------------------------------
// Universal TN GEMM: C = scale*(A @ B^T) + bias ; optional causal / K-limit
// A: [M,K] lda ; B: [N,K] ldb ; C: [M,N] ldc ; batch via blockIdx.z strides.
// BIAS: 0 none, 1 bias[col], 2 bias[row].
// CAUSAL: mask col>row to -inf, skip tiles fully above diagonal.
// KLIM: k-loop runs only to bm0+BM (attn cols beyond are exactly 0).
// All dims are multiples of 128/32 for this problem.
// ---------------------------------------------------------------------------
template <int BIAS, bool CAUSAL, bool KLIM>
__global__ void __launch_bounds__(NT, 1)
mma_tn(const float* __restrict__ A, const float* __restrict__ B,
       const float* __restrict__ bias, float* __restrict__ C,
       int K, int lda, int ldb, int ldc, float scale,
       long sA, long sB, long sC)
{
    const int bm0 = blockIdx.y * BM;
    const int bn0 = blockIdx.x * BN;
    A += (long)blockIdx.z * sA;
    B += (long)blockIdx.z * sB;
    C += (long)blockIdx.z * sC;

    const int tid  = threadIdx.x;
    const int lane = tid & 31;
    const int wid  = tid >> 5;
    const int wm0  = (wid & 3) * 32;    // warp tile: 32 (M) x 64 (N)
    const int wn0  = (wid >> 2) * 64;
    const int lq   = lane >> 2;         // 0..7
    const int lr   = lane & 3;          // 0..3

    if (CAUSAL && bn0 >= bm0 + BM) {
        // Tile strictly above diagonal: all -inf, skip compute.
        const float2 mi = make_float2(-INFINITY, -INFINITY);
        #pragma unroll
        for (int mt = 0; mt < 2; ++mt)
            #pragma unroll
            for (int nt = 0; nt < 8; ++nt) {
                const int r0 = bm0 + wm0 + mt * 16 + lq;
                const int c0 = bn0 + wn0 + nt * 8 + 2 * lr;
                *(float2*)(C + (long)r0 * ldc + c0) = mi;
                *(float2*)(C + (long)(r0 + 8) * ldc + c0) = mi;
            }
        return;
    }

    extern __shared__ uint32_t sm[];

    float acc[2][8][4] = {};

    const int kend  = KLIM ? (bm0 + BM) : K;
    const int niter = kend / BK;

    // global staging map: row = tid>>1 (0..127), k-half = (tid&1)*16
    const int gr = tid >> 1;
    const int gk = (tid & 1) * 16;
    const int sbase = gr * QS + (gk >> 1);

    const float* Ag = A + (long)(bm0 + gr) * lda + gk;
    const float* Bg = B + (long)(bn0 + gr) * ldb + gk;

    float4 ra[4], rb[4];
    #pragma unroll
    for (int j = 0; j < 4; ++j) {
        ra[j] = *(const float4*)(Ag + 4 * j);
        rb[j] = *(const float4*)(Bg + 4 * j);
    }
    store_tile(sm, ra, rb, sbase);
    __syncthreads();

    for (int it = 0; it < niter; ++it) {
        const uint32_t* buf = sm + (it & 1) * 4 * TILE_W;

        const bool pf = (it + 1 < niter);
        if (pf) {
            const float* An = Ag + (long)(it + 1) * BK;
            const float* Bn = Bg + (long)(it + 1) * BK;
            #pragma unroll
            for (int j = 0; j < 4; ++j) {
                ra[j] = *(const float4*)(An + 4 * j);
                rb[j] = *(const float4*)(Bn + 4 * j);
            }
        }

        #pragma unroll
        for (int ks = 0; ks < 2; ++ks) {
            const int q0 = ks * 8 + lr;

            uint32_t ahi[2][4], alo[2][4];
            #pragma unroll
            for (int mt = 0; mt < 2; ++mt) {
                const int m = wm0 + mt * 16 + lq;
                const uint32_t* ph = buf + m * QS;
                const uint32_t* pl = ph + TILE_W;
                ahi[mt][0] = ph[q0];               alo[mt][0] = pl[q0];
                ahi[mt][1] = ph[8 * QS + q0];      alo[mt][1] = pl[8 * QS + q0];
                ahi[mt][2] = ph[q0 + 4];           alo[mt][2] = pl[q0 + 4];
                ahi[mt][3] = ph[8 * QS + q0 + 4];  alo[mt][3] = pl[8 * QS + q0 + 4];
            }

            #pragma unroll
            for (int nt = 0; nt < 8; ++nt) {
                const int n = wn0 + nt * 8 + lq;
                const uint32_t* ph = buf + 2 * TILE_W + n * QS;
                const uint32_t* pl = ph + TILE_W;
                const uint32_t bh0 = ph[q0], bh1 = ph[q0 + 4];
                const uint32_t bl0 = pl[q0], bl1 = pl[q0 + 4];
                #pragma unroll
                for (int mt = 0; mt < 2; ++mt) {
                    float* c = acc[mt][nt];
                    mma_bf16(c, alo[mt][0], alo[mt][1], alo[mt][2], alo[mt][3], bh0, bh1);
                    mma_bf16(c, ahi[mt][0], ahi[mt][1], ahi[mt][2], ahi[mt][3], bl0, bl1);
                    mma_bf16(c, ahi[mt][0], ahi[mt][1], ahi[mt][2], ahi[mt][3], bh0, bh1);
                }
            }
        }

        if (pf)
            store_tile(sm + ((it + 1) & 1) * 4 * TILE_W, ra, rb, sbase);
        __syncthreads();
    }

    // epilogue
    #pragma unroll
    for (int mt = 0; mt < 2; ++mt)
        #pragma unroll
        for (int nt = 0; nt < 8; ++nt) {
            const int r0 = bm0 + wm0 + mt * 16 + lq;
            const int c0 = bn0 + wn0 + nt * 8 + 2 * lr;
            float v00 = acc[mt][nt][0] * scale;
            float v01 = acc[mt][nt][1] * scale;
            float v10 = acc[mt][nt][2] * scale;
            float v11 = acc[mt][nt][3] * scale;
            if (BIAS == 1) {
                const float b0 = bias[c0], b1 = bias[c0 + 1];
                v00 += b0; v01 += b1; v10 += b0; v11 += b1;
            }
            if (BIAS == 2) {
                const float br0 = bias[r0], br1 = bias[r0 + 8];
                v00 += br0; v01 += br0; v10 += br1; v11 += br1;
            }
            if (CAUSAL) {
                if (c0 > r0)         v00 = -INFINITY;
                if (c0 + 1 > r0)     v01 = -INFINITY;
                if (c0 > r0 + 8)     v10 = -INFINITY;
                if (c0 + 1 > r0 + 8) v11 = -INFINITY;
            }
            *(float2*)(C + (long)r0 * ldc + c0) = make_float2(v00, v01);
            *(float2*)(C + (long)(r0 + 8) * ldc + c0) = make_float2(v10, v11);
        }
}

// ---------------------------------------------------------------------------
// Row softmax over 2048 columns; one block (256 threads) per row.
// ---------------------------------------------------------------------------
__global__ void __launch_bounds__(256)
softmax_kernel(float* __restrict__ S)
{
    const long row = blockIdx.x;
    float* p = S + row * 2048L;
    const int tid = threadIdx.x;

    float v[8];
    float m = -INFINITY;
    #pragma unroll
    for (int i = 0; i < 8; ++i) {
        v[i] = p[tid + i * 256];
        m = fmaxf(m, v[i]);
    }
    #pragma unroll
    for (int o = 16; o > 0; o >>= 1)
        m = fmaxf(m, __shfl_xor_sync(0xffffffffu, m, o));

    __shared__ float red[8];
    if ((tid & 31) == 0) red[tid >> 5] = m;
    __syncthreads();
    float mg = red[0];
    #pragma unroll
    for (int w = 1; w < 8; ++w) mg = fmaxf(mg, red[w]);

    float sum = 0.0f;
    #pragma unroll
    for (int i = 0; i < 8; ++i) {
        v[i] = __expf(v[i] - mg);
        sum += v[i];
    }
    #pragma unroll
    for (int o = 16; o > 0; o >>= 1)
        sum += __shfl_xor_sync(0xffffffffu, sum, o);
    __syncthreads();
    if ((tid & 31) == 0) red[tid >> 5] = sum;
    __syncthreads();
    float tot = 0.0f;
    #pragma unroll
    for (int w = 0; w < 8; ++w) tot += red[w];
    const float inv = 1.0f / tot;

    #pragma unroll
    for (int i = 0; i < 8; ++i)
        p[tid + i * 256] = v[i] * inv;
}

// ---------------------------------------------------------------------------
// Launch
// ---------------------------------------------------------------------------
extern "C" void kernel_launch(void* const* d_in, const int* in_sizes, int n_in,
                              void* d_out, int out_size)
{
    const float* x  = (const float*)d_in[0];
    // d_in[1] is the causal tril mask -> applied analytically.
    const float* Wq = (const float*)d_in[2];
    const float* bq = (const float*)d_in[3];
    const float* Wk = (const float*)d_in[4];
    const float* bk = (const float*)d_in[5];
    const float* Wv = (const float*)d_in[6];
    const float* bv = (const float*)d_in[7];
    const float* Wp = (const float*)d_in[8];
    const float* bp = (const float*)d_in[9];
    float* out = (float*)d_out;

    float *qc, *k, *vt, *s;
    cudaGetSymbolAddress((void**)&qc, g_qc);
    cudaGetSymbolAddress((void**)&k,  g_k);
    cudaGetSymbolAddress((void**)&vt, g_vt);
    cudaGetSymbolAddress((void**)&s,  g_s);

    // opt-in >48KB dynamic smem (host-side config; idempotent, capture-safe)
    cudaFuncSetAttribute(mma_tn<1, false, false>,
                         cudaFuncAttributeMaxDynamicSharedMemorySize, SMEM_BYTES);
    cudaFuncSetAttribute(mma_tn<2, false, false>,
                         cudaFuncAttributeMaxDynamicSharedMemorySize, SMEM_BYTES);
    cudaFuncSetAttribute(mma_tn<0, true, false>,
                         cudaFuncAttributeMaxDynamicSharedMemorySize, SMEM_BYTES);
    cudaFuncSetAttribute(mma_tn<0, false, true>,
                         cudaFuncAttributeMaxDynamicSharedMemorySize, SMEM_BYTES);

    const int Bt = 4, S2 = 2048, D = 2048;
    const int Mtot = Bt * S2;                 // 8192
    const long ts = (long)S2 * D;             // token-batch stride
    const long bs = (long)S2 * S2;            // scores batch stride
    const float inv_std = 1.0f / sqrtf((float)D);

    dim3 blk(NT);
    dim3 gproj(D / BN, Mtot / BM, 1);         // (16, 64)
    dim3 gvt(Mtot / BN, D / BM, 1);           // (64, 16)
    dim3 gattn(S2 / BN, S2 / BM, Bt);         // (16, 16, 4)

    // q = x @ Wq^T + bq ; k = x @ Wk^T + bk
    mma_tn<1, false, false><<<gproj, blk, SMEM_BYTES>>>(
        x, Wq, bq, qc, D, D, D, D, 1.0f, 0, 0, 0);
    mma_tn<1, false, false><<<gproj, blk, SMEM_BYTES>>>(
        x, Wk, bk, k, D, D, D, D, 1.0f, 0, 0, 0);

    // vt[d, t] = sum_e Wv[d,e] x[t,e] + bv[d]  (V transposed, row bias)
    mma_tn<2, false, false><<<gvt, blk, SMEM_BYTES>>>(
        Wv, x, bv, vt, D, D, D, Mtot, 1.0f, 0, 0, 0);

    // scores = (q @ k^T) * inv_std, causal (-inf above diagonal)
    mma_tn<0, true, false><<<gattn, blk, SMEM_BYTES>>>(
        qc, k, nullptr, s, D, D, D, S2, inv_std, ts, ts, bs);

    // softmax rows
    softmax_kernel<<<Bt * S2, 256>>>(s);

    // ctx[q,d] = sum_k attn[q,k] vt[d, z*S2 + k]   (K-limited by causality)
    // ctx overwrites qc (q is dead). B batch offset = z*S2 columns.
    mma_tn<0, false, true><<<gattn, blk, SMEM_BYTES>>>(
        s, vt, nullptr, qc, S2, S2, Mtot, D, 1.0f, bs, S2, ts);

    // out = ctx @ Wp^T + bp
    mma_tn<1, false, false><<<gproj, blk, SMEM_BYTES>>>(
        qc, Wp, bp, out, D, D, D, D, 1.0f, 0, 0, 0);
}

// round 11
// speedup vs baseline: 2.9026x; 1.1831x over previous
#include <cuda_runtime.h>
#include <cuda_bf16.h>
#include <math.h>
#include <stdint.h>

// ---------------------------------------------------------------------------
// Attention_51977694216863 (B=4, S=2048, D=2048, fp32).
// tcgen05 unavailable (harness lowers via compute_103 virtual arch) ->
// mma.sync bf16x3 pipeline:
//   - operands pre-split to bf16 hi/lo in gmem (no CVT in GEMM mainloop)
//   - ldmatrix.x4 fragment loads (SW64 swizzle, conflict-free)
//   - cp.async.cg 3-stage pipeline, BK=32
//   - epilogues write bf16 hi/lo directly where consumer is a GEMM
// Scratch: ONE pooled __device__ buffer, 285MB peak via liveness reuse
// (round-10's 521MB footprint suspected in container failure; 268MB proven).
// C = scale*(A @ B^T)[+bias][causal|K-limit]; D += Alo*Bhi + Ahi*Blo + Ahi*Bhi
// ---------------------------------------------------------------------------

#define BM 128
#define BN 128
#define BK 32
#define NT 256
#define STAGES 3
#define PART_BYTES  8192                   // 128 rows x 32 bf16 x 2B
#define STAGE_BYTES (4 * PART_BYTES)       // Ah, Al, Bh, Bl
#define SMEM_TOTAL  (STAGES * STAGE_BYTES) // 98304 B

// ---------------------------------------------------------------------------
// Pooled scratch (allocation-free rule: one __device__ global).
// unit U = 8192*2048 bf16 = 33.55MB
//   [0,2U)   : xh, xl          -> later reused as fp32 scores s (2U = 67MB)
//   [2U,4U)  : qh, ql          -> later reused as attn hi/lo
//   [4U,6U)  : kh, kl          -> later reused as ctx hi/lo
//   [6U,8U)  : vth, vtl
//   [8U, +2W): wh, wl (W = 2048*2048*2B = 8.4MB), re-split per projection
// ---------------------------------------------------------------------------
#define UNIT (8192L * 2048 * 2)            // bytes per half-tensor
#define WUNIT (2048L * 2048 * 2)
__device__ __align__(256) uint8_t g_pool[8 * UNIT + 2 * WUNIT];

// ---------------------------------------------------------------------------
// helpers
// ---------------------------------------------------------------------------
__device__ __forceinline__ uint32_t smem_u32(const void* p) {
    uint32_t a;
    asm("{ .reg .u64 t; cvta.to.shared.u64 t, %1; cvt.u32.u64 %0, t; }"
        : "=r"(a) : "l"(p));
    return a;
}

__device__ __forceinline__ uint32_t cvt_bf16x2(float lo_e, float hi_e) {
    uint32_t r;
    asm("cvt.rn.bf16x2.f32 %0, %1, %2;" : "=r"(r) : "f"(hi_e), "f"(lo_e));
    return r;  // low half = lo_e, high half = hi_e
}
// split (e0,e1) into packed bf16x2 hi/lo parts
__device__ __forceinline__ void split2(float e0, float e1, uint32_t& hi, uint32_t& lo) {
    uint32_t h = cvt_bf16x2(e0, e1);
    float f0 = __uint_as_float(h << 16);
    float f1 = __uint_as_float(h & 0xffff0000u);
    lo = cvt_bf16x2(e0 - f0, e1 - f1);
    hi = h;
}

__device__ __forceinline__ void mma_bf16(float* c, uint32_t a0, uint32_t a1,
                                         uint32_t a2, uint32_t a3,
                                         uint32_t b0, uint32_t b1) {
    asm volatile(
        "mma.sync.aligned.m16n8k16.row.col.f32.bf16.bf16.f32 "
        "{%0,%1,%2,%3}, {%4,%5,%6,%7}, {%8,%9}, {%0,%1,%2,%3};"
        : "+f"(c[0]), "+f"(c[1]), "+f"(c[2]), "+f"(c[3])
        : "r"(a0), "r"(a1), "r"(a2), "r"(a3), "r"(b0), "r"(b1));
}

__device__ __forceinline__ void ldsm4(uint32_t& r0, uint32_t& r1,
                                      uint32_t& r2, uint32_t& r3, uint32_t addr) {
    asm volatile("ldmatrix.sync.aligned.m8n8.x4.shared.b16 {%0,%1,%2,%3}, [%4];"
                 : "=r"(r0), "=r"(r1), "=r"(r2), "=r"(r3) : "r"(addr));
}

__device__ __forceinline__ void cp16(uint32_t dst, const void* src) {
    asm volatile("cp.async.cg.shared.global [%0], [%1], 16;"
                 :: "r"(dst), "l"(src));
}
__device__ __forceinline__ void cp_commit() {
    asm volatile("cp.async.commit_group;" ::: "memory");
}
__device__ __forceinline__ void cp_wait1() {
    asm volatile("cp.async.wait_group 1;" ::: "memory");
}

// SW64 swizzle term for a 64B row: s(row) = ((row>>1)&3)<<4
__device__ __forceinline__ uint32_t srow(int row) { return ((row >> 1) & 3) << 4; }

// ---------------------------------------------------------------------------
// elementwise fp32 -> bf16 hi/lo split
// ---------------------------------------------------------------------------
__global__ void __launch_bounds__(256)
split_kernel(const float* __restrict__ src, uint16_t* __restrict__ hi,
             uint16_t* __restrict__ lo, long n4)
{
    long i = (long)blockIdx.x * 256 + threadIdx.x;
    if (i >= n4) return;
    float4 v = ((const float4*)src)[i];
    uint32_t h0, l0, h1, l1;
    split2(v.x, v.y, h0, l0);
    split2(v.z, v.w, h1, l1);
    ((uint2*)hi)[i] = make_uint2(h0, h1);
    ((uint2*)lo)[i] = make_uint2(l0, l1);
}

// ---------------------------------------------------------------------------
// TN GEMM, bf16 hi/lo inputs, fp32 accum.
// A: [M,K] lda ; B: [N,K] ldb ; C: [M,N] ldc ; batch via blockIdx.z strides.
// BIAS: 0 none, 1 bias[col], 2 bias[row].
// CAUSAL: mask col>row -inf + skip upper tiles (fp32 out only).
// KLIM: K loop to bm0+BM. SPLIT: write bf16 hi/lo C, else fp32.
// ---------------------------------------------------------------------------
template <int BIAS, bool CAUSAL, bool KLIM, bool SPLIT>
__global__ void __launch_bounds__(NT, 1)
mm(const uint16_t* __restrict__ Agh, const uint16_t* __restrict__ Agl,
   const uint16_t* __restrict__ Bgh, const uint16_t* __restrict__ Bgl,
   const float* __restrict__ bias, float* __restrict__ Cf,
   uint16_t* __restrict__ Ch, uint16_t* __restrict__ Cl,
   int K, int lda, int ldb, int ldc, float scale,
   long sA, long sB, long sC)
{
    const int bm0 = blockIdx.y * BM;
    const int bn0 = blockIdx.x * BN;
    const int tid = threadIdx.x;
    const int lane = tid & 31;
    const int wid = tid >> 5;

    Agh += (long)blockIdx.z * sA;  Agl += (long)blockIdx.z * sA;
    Bgh += (long)blockIdx.z * sB;  Bgl += (long)blockIdx.z * sB;
    const long czoff = (long)blockIdx.z * sC;

    if (CAUSAL && bn0 >= bm0 + BM) {
        // Entire tile strictly above diagonal: -inf fill, skip compute.
        float* C = Cf + czoff;
        const float2 mi = make_float2(-INFINITY, -INFINITY);
        for (int i = tid; i < 128 * 64; i += NT) {
            const int r = i >> 6;
            const int c = (i & 63) * 2;
            *(float2*)(C + (long)(bm0 + r) * ldc + bn0 + c) = mi;
        }
        return;
    }

    extern __shared__ char smem[];
    const uint32_t sb0 = smem_u32(smem);

    // ---- loader mapping: thread t covers one 16B chunk of 2 rows per part ----
    const int lr0 = tid >> 2;            // rows 0..63
    const int lr1 = lr0 + 64;            // rows 64..127
    const int lc  = tid & 3;             // 16B chunk within 64B row
    const uint32_t sw0 = lr0 * 64 + ((lc << 4) ^ srow(lr0));
    const uint32_t sw1 = lr1 * 64 + ((lc << 4) ^ srow(lr1));
    const uint16_t* A0h = Agh + (long)(bm0 + lr0) * lda + lc * 8;
    const uint16_t* A1h = Agh + (long)(bm0 + lr1) * lda + lc * 8;
    const uint16_t* A0l = Agl + (long)(bm0 + lr0) * lda + lc * 8;
    const uint16_t* A1l = Agl + (long)(bm0 + lr1) * lda + lc * 8;
    const uint16_t* B0h = Bgh + (long)(bn0 + lr0) * ldb + lc * 8;
    const uint16_t* B1h = Bgh + (long)(bn0 + lr1) * ldb + lc * 8;
    const uint16_t* B0l = Bgl + (long)(bn0 + lr0) * ldb + lc * 8;
    const uint16_t* B1l = Bgl + (long)(bn0 + lr1) * ldb + lc * 8;

    auto issue = [&](int stg, int k0) {
        const uint32_t sb = sb0 + stg * STAGE_BYTES;
        cp16(sb                  + sw0, A0h + k0);
        cp16(sb                  + sw1, A1h + k0);
        cp16(sb +     PART_BYTES + sw0, A0l + k0);
        cp16(sb +     PART_BYTES + sw1, A1l + k0);
        cp16(sb + 2 * PART_BYTES + sw0, B0h + k0);
        cp16(sb + 2 * PART_BYTES + sw1, B1h + k0);
        cp16(sb + 3 * PART_BYTES + sw0, B0l + k0);
        cp16(sb + 3 * PART_BYTES + sw1, B1l + k0);
    };

    // ---- ldmatrix address precompute ----
    // warp tile: 32(M) x 64(N); fr = row-in-16, cb = k-chunk parity
    const int m0 = (wid & 3) * 32;
    const int n0 = (wid >> 2) * 64;
    const int fr = (lane & 7) + ((lane >> 3) & 1) * 8;
    const int cb = (lane >> 4) & 1;
    uint32_t aoff[2][2], boff[4][2];
    #pragma unroll
    for (int mt = 0; mt < 2; ++mt) {
        const int row = m0 + mt * 16 + fr;
        const uint32_t s = srow(row);
        aoff[mt][0] = row * 64 + (((0 + cb) << 4) ^ s);
        aoff[mt][1] = row * 64 + (((2 + cb) << 4) ^ s);
    }
    #pragma unroll
    for (int n4 = 0; n4 < 4; ++n4) {
        const int row = n0 + n4 * 16 + fr;
        const uint32_t s = srow(row);
        boff[n4][0] = row * 64 + (((0 + cb) << 4) ^ s);
        boff[n4][1] = row * 64 + (((2 + cb) << 4) ^ s);
    }

    float acc[2][8][4] = {};

    const int kend  = KLIM ? (bm0 + BM) : K;
    const int niter = kend / BK;           // >= 4 always here

    issue(0, 0);      cp_commit();
    issue(1, BK);     cp_commit();

    for (int it = 0; it < niter; ++it) {
        cp_wait1();
        __syncthreads();
        const int nx = it + 2;
        if (nx < niter) issue(nx % STAGES, nx * BK);
        cp_commit();

        const uint32_t sb = sb0 + (it % STAGES) * STAGE_BYTES;
        #pragma unroll
        for (int ks = 0; ks < 2; ++ks) {
            uint32_t ah[2][4], al[2][4], bh[4][4], bl[4][4];
            #pragma unroll
            for (int mt = 0; mt < 2; ++mt) {
                ldsm4(ah[mt][0], ah[mt][1], ah[mt][2], ah[mt][3],
                      sb + aoff[mt][ks]);
                ldsm4(al[mt][0], al[mt][1], al[mt][2], al[mt][3],
                      sb + PART_BYTES + aoff[mt][ks]);
            }
            #pragma unroll
            for (int n4 = 0; n4 < 4; ++n4) {
                ldsm4(bh[n4][0], bh[n4][1], bh[n4][2], bh[n4][3],
                      sb + 2 * PART_BYTES + boff[n4][ks]);
                ldsm4(bl[n4][0], bl[n4][1], bl[n4][2], bl[n4][3],
                      sb + 3 * PART_BYTES + boff[n4][ks]);
            }
            #pragma unroll
            for (int nt = 0; nt < 8; ++nt) {
                const int n4 = nt >> 1, sl = nt & 1;
                const uint32_t b0h = bh[n4][sl], b1h = bh[n4][2 + sl];
                const uint32_t b0l = bl[n4][sl], b1l = bl[n4][2 + sl];
                #pragma unroll
                for (int mt = 0; mt < 2; ++mt) {
                    float* c = acc[mt][nt];
                    mma_bf16(c, al[mt][0], al[mt][1], al[mt][2], al[mt][3], b0h, b1h);
                    mma_bf16(c, ah[mt][0], ah[mt][1], ah[mt][2], ah[mt][3], b0l, b1l);
                    mma_bf16(c, ah[mt][0], ah[mt][1], ah[mt][2], ah[mt][3], b0h, b1h);
                }
            }
        }
    }

    // ---- epilogue ----
    const int g  = lane >> 2;
    const int tg = lane & 3;
    #pragma unroll
    for (int mt = 0; mt < 2; ++mt)
        #pragma unroll
        for (int nt = 0; nt < 8; ++nt) {
            const int r = bm0 + m0 + mt * 16 + g;
            const int c = bn0 + n0 + nt * 8 + tg * 2;
            float v0 = acc[mt][nt][0] * scale;
            float v1 = acc[mt][nt][1] * scale;
            float v2 = acc[mt][nt][2] * scale;
            float v3 = acc[mt][nt][3] * scale;
            if (BIAS == 1) {
                const float b0 = bias[c], b1 = bias[c + 1];
                v0 += b0; v1 += b1; v2 += b0; v3 += b1;
            }
            if (BIAS == 2) {
                const float br0 = bias[r], br1 = bias[r + 8];
                v0 += br0; v1 += br0; v2 += br1; v3 += br1;
            }
            if (SPLIT) {
                uint16_t* ch = Ch + czoff;
                uint16_t* cl = Cl + czoff;
                uint32_t h, l;
                split2(v0, v1, h, l);
                *(uint32_t*)(ch + (long)r * ldc + c) = h;
                *(uint32_t*)(cl + (long)r * ldc + c) = l;
                split2(v2, v3, h, l);
                *(uint32_t*)(ch + (long)(r + 8) * ldc + c) = h;
                *(uint32_t*)(cl + (long)(r + 8) * ldc + c) = l;
            } else {
                if (CAUSAL) {
                    if (c > r)         v0 = -INFINITY;
                    if (c + 1 > r)     v1 = -INFINITY;
                    if (c > r + 8)     v2 = -INFINITY;
                    if (c + 1 > r + 8) v3 = -INFINITY;
                }
                float* C = Cf + czoff;
                *(float2*)(C + (long)r * ldc + c) = make_float2(v0, v1);
                *(float2*)(C + (long)(r + 8) * ldc + c) = make_float2(v2, v3);
            }
        }
}

// ---------------------------------------------------------------------------
// Row softmax over 2048 cols; writes attn as bf16 hi/lo. One block per row.
// ---------------------------------------------------------------------------
__global__ void __launch_bounds__(256)
softmax_split(const float* __restrict__ S, uint16_t* __restrict__ Ah,
              uint16_t* __restrict__ Al)
{
    const long row = blockIdx.x;
    const float* p = S + row * 2048L;
    const int tid = threadIdx.x;

    float4 va = ((const float4*)p)[tid * 2];
    float4 vb = ((const float4*)p)[tid * 2 + 1];
    float v[8] = {va.x, va.y, va.z, va.w, vb.x, vb.y, vb.z, vb.w};

    float m = -INFINITY;
    #pragma unroll
    for (int i = 0; i < 8; ++i) m = fmaxf(m, v[i]);
    #pragma unroll
    for (int o = 16; o > 0; o >>= 1)
        m = fmaxf(m, __shfl_xor_sync(0xffffffffu, m, o));

    __shared__ float red[8];
    if ((tid & 31) == 0) red[tid >> 5] = m;
    __syncthreads();
    float mg = red[0];
    #pragma unroll
    for (int w = 1; w < 8; ++w) mg = fmaxf(mg, red[w]);

    float sum = 0.0f;
    #pragma unroll
    for (int i = 0; i < 8; ++i) {
        v[i] = __expf(v[i] - mg);
        sum += v[i];
    }
    #pragma unroll
    for (int o = 16; o > 0; o >>= 1)
        sum += __shfl_xor_sync(0xffffffffu, sum, o);
    __syncthreads();
    if ((tid & 31) == 0) red[tid >> 5] = sum;
    __syncthreads();
    float tot = 0.0f;
    #pragma unroll
    for (int w = 0; w < 8; ++w) tot += red[w];
    const float inv = 1.0f / tot;

    uint32_t* oh = (uint32_t*)(Ah + row * 2048L) + tid * 4;
    uint32_t* ol = (uint32_t*)(Al + row * 2048L) + tid * 4;
    #pragma unroll
    for (int j = 0; j < 4; ++j) {
        uint32_t h, l;
        split2(v[2 * j] * inv, v[2 * j + 1] * inv, h, l);
        oh[j] = h;
        ol[j] = l;
    }
}

// ---------------------------------------------------------------------------
// Launch
// ---------------------------------------------------------------------------
extern "C" void kernel_launch(void* const* d_in, const int* in_sizes, int n_in,
                              void* d_out, int out_size)
{
    const float* x  = (const float*)d_in[0];
    // d_in[1] is the causal tril mask -> applied analytically.
    const float* Wq = (const float*)d_in[2];
    const float* bq = (const float*)d_in[3];
    const float* Wk = (const float*)d_in[4];
    const float* bk = (const float*)d_in[5];
    const float* Wv = (const float*)d_in[6];
    const float* bv = (const float*)d_in[7];
    const float* Wp = (const float*)d_in[8];
    const float* bp = (const float*)d_in[9];
    float* out = (float*)d_out;

    uint8_t* pool;
    cudaGetSymbolAddress((void**)&pool, g_pool);

    // pool carving (liveness-based reuse)
    uint16_t* xh  = (uint16_t*)(pool + 0 * UNIT);
    uint16_t* xl  = (uint16_t*)(pool + 1 * UNIT);
    uint16_t* qh  = (uint16_t*)(pool + 2 * UNIT);
    uint16_t* ql  = (uint16_t*)(pool + 3 * UNIT);
    uint16_t* kh  = (uint16_t*)(pool + 4 * UNIT);
    uint16_t* kl  = (uint16_t*)(pool + 5 * UNIT);
    uint16_t* vth = (uint16_t*)(pool + 6 * UNIT);
    uint16_t* vtl = (uint16_t*)(pool + 7 * UNIT);
    uint16_t* wh  = (uint16_t*)(pool + 8 * UNIT);
    uint16_t* wl  = (uint16_t*)(pool + 8 * UNIT + WUNIT);
    float*    s   = (float*)   (pool + 0 * UNIT);   // reuses x (dead)
    uint16_t* ah  = qh;                             // attn reuses q (dead)
    uint16_t* al  = ql;
    uint16_t* ch  = kh;                             // ctx reuses k (dead)
    uint16_t* cl  = kl;

    cudaFuncSetAttribute(mm<1, false, false, true>,
                         cudaFuncAttributeMaxDynamicSharedMemorySize, SMEM_TOTAL);
    cudaFuncSetAttribute(mm<2, false, false, true>,
                         cudaFuncAttributeMaxDynamicSharedMemorySize, SMEM_TOTAL);
    cudaFuncSetAttribute(mm<0, true, false, false>,
                         cudaFuncAttributeMaxDynamicSharedMemorySize, SMEM_TOTAL);
    cudaFuncSetAttribute(mm<0, false, true, true>,
                         cudaFuncAttributeMaxDynamicSharedMemorySize, SMEM_TOTAL);
    cudaFuncSetAttribute(mm<1, false, false, false>,
                         cudaFuncAttributeMaxDynamicSharedMemorySize, SMEM_TOTAL);

    const int Bt = 4, S2 = 2048, D = 2048;
    const int Mtot = Bt * S2;                  // 8192
    const long ts = (long)S2 * D;              // token-batch stride (elements)
    const long bs = (long)S2 * S2;             // scores batch stride
    const long wsz = (long)D * D;
    const float inv_std = 1.0f / sqrtf((float)D);

    dim3 blk(NT);
    dim3 gproj(D / BN, Mtot / BM, 1);          // (16, 64)
    dim3 gvt(Mtot / BN, D / BM, 1);            // (64, 16)
    dim3 gattn(S2 / BN, S2 / BM, Bt);          // (16, 16, 4)
    const unsigned gsx  = (unsigned)(ts * Bt / 4 / 256);
    const unsigned gsw  = (unsigned)(wsz / 4 / 256);

    // x split (used by q, k, vt)
    split_kernel<<<gsx, 256>>>(x, xh, xl, ts * Bt / 4);

    // q = x @ Wq^T + bq  (split Wq into the shared w pair first)
    split_kernel<<<gsw, 256>>>(Wq, wh, wl, wsz / 4);
    mm<1, false, false, true><<<gproj, blk, SMEM_TOTAL>>>(
        xh, xl, wh, wl, bq, nullptr, qh, ql, D, D, D, D, 1.0f, 0, 0, 0);

    // k = x @ Wk^T + bk
    split_kernel<<<gsw, 256>>>(Wk, wh, wl, wsz / 4);
    mm<1, false, false, true><<<gproj, blk, SMEM_TOTAL>>>(
        xh, xl, wh, wl, bk, nullptr, kh, kl, D, D, D, D, 1.0f, 0, 0, 0);

    // vt[d,t] = sum_e Wv[d,e] x[t,e] + bv[d]  (V transposed, row bias)
    split_kernel<<<gsw, 256>>>(Wv, wh, wl, wsz / 4);
    mm<2, false, false, true><<<gvt, blk, SMEM_TOTAL>>>(
        wh, wl, xh, xl, bv, nullptr, vth, vtl, D, D, D, Mtot, 1.0f, 0, 0, 0);

    // scores = (q @ k^T) * inv_std, causal, fp32 out (into x's region; x dead)
    mm<0, true, false, false><<<gattn, blk, SMEM_TOTAL>>>(
        qh, ql, kh, kl, nullptr, s, nullptr, nullptr,
        D, D, D, S2, inv_std, ts, ts, bs);

    // softmax rows -> attn hi/lo (into q's region; q dead)
    softmax_split<<<Bt * S2, 256>>>(s, ah, al);

    // ctx[q,d] = sum_k attn[q,k] vt[d, z*S2+k]  (K-limited; into k's region)
    mm<0, false, true, true><<<gattn, blk, SMEM_TOTAL>>>(
        ah, al, vth, vtl, nullptr, nullptr, ch, cl,
        S2, S2, Mtot, D, 1.0f, bs, S2, ts);

    // out = ctx @ Wp^T + bp  (fp32 out)
    split_kernel<<<gsw, 256>>>(Wp, wh, wl, wsz / 4);
    mm<1, false, false, false><<<gproj, blk, SMEM_TOTAL>>>(
        ch, cl, wh, wl, bp, out, nullptr, nullptr, D, D, D, D, 1.0f, 0, 0, 0);
}